// round 17
// baseline (speedup 1.0000x reference)
#include <cuda_runtime.h>
#include <cuda_bf16.h>
#include <cuda_fp16.h>
#include <math.h>
#include <stdint.h>

#define DEV_INLINE __device__ __forceinline__

// Problem constants
constexpr int Mdim = 768;
constexpr int Vv   = 32000;
constexpr int Rr   = 48;
constexpr int Nn   = 16;
constexpr int Kk   = 4;
constexpr int Ll   = 2;
constexpr int Hh   = 1536;
constexpr int Bb   = 2;
constexpr int Ss   = 1024;
constexpr int BS   = Bb * Ss;     // 2048
constexpr int H2   = 2 * Hh;      // 3072
constexpr int XD   = Rr + 2 * Nn; // 80

constexpr int K2_M  = Mdim / 2;   // 384
constexpr int K2_H  = Hh / 2;     // 768
constexpr int K2_DT = 32;         // 48/2=24 -> pad 32
constexpr int LXR   = 128;        // lxw plane rows (80 real + 48 zero)

// ---------------- fp32 scratch ----------------
__device__ float g_x    [BS * Mdim];
__device__ float g_xr   [BS * H2];
__device__ float g_delta[BS * Hh];
__device__ float g_mo   [BS * Mdim];
__device__ float g_xw   [BS * LXR];                // linx raw output (pre-bias)
__device__ float g_zb   [LXR];                     // zero bias (static zero-init)
__device__ __align__(16) float2 g_ures[BS * Hh];   // {u, res} per (row,h)

// ---------------- packed 16-bit planes ----------------
__device__ __align__(16) uint32_t g_xp_h [BS * K2_M];
__device__ __align__(16) uint32_t g_xp_l [BS * K2_M];
__device__ __align__(16) uint32_t g_uh   [BS * K2_H];
__device__ __align__(16) uint32_t g_ul   [BS * K2_H];
__device__ __align__(16) uint32_t g_act_h[BS * K2_H];
__device__ __align__(16) uint32_t g_act_l[BS * K2_H];
__device__ __align__(16) uint32_t g_liw_h[Ll * H2 * K2_M];
__device__ __align__(16) uint32_t g_liw_l[Ll * H2 * K2_M];
__device__ __align__(16) uint32_t g_ldw_h[Ll * Hh * K2_DT];
__device__ __align__(16) uint32_t g_ldw_l[Ll * Hh * K2_DT];
__device__ __align__(16) uint32_t g_low_h[Ll * Mdim * K2_H];
__device__ __align__(16) uint32_t g_low_l[Ll * Mdim * K2_H];
__device__ __align__(16) uint32_t g_lxw_h[Ll * LXR * K2_H];
__device__ __align__(16) uint32_t g_lxw_l[Ll * LXR * K2_H];
__device__ __align__(16) uint32_t g_hw_h [Vv * K2_M];

// ---------------- helpers ----------------
DEV_INLINE float silu_fast(float v)  { return v / (1.f + __expf(-v)); }
DEV_INLINE float softplusf(float v)  { return v > 20.f ? v : log1pf(expf(v)); }

DEV_INLINE float warp_sum(float v) {
    #pragma unroll
    for (int o = 16; o; o >>= 1) v += __shfl_xor_sync(0xffffffffu, v, o);
    return v;
}

DEV_INLINE uint32_t packsplit(float f0, float f1, uint32_t& lo) {
    __nv_bfloat16 h0 = __float2bfloat16(f0);
    __nv_bfloat16 h1 = __float2bfloat16(f1);
    __nv_bfloat16 l0 = __float2bfloat16(f0 - __bfloat162float(h0));
    __nv_bfloat16 l1 = __float2bfloat16(f1 - __bfloat162float(h1));
    lo = (uint32_t)__bfloat16_as_ushort(l0) | ((uint32_t)__bfloat16_as_ushort(l1) << 16);
    return (uint32_t)__bfloat16_as_ushort(h0) | ((uint32_t)__bfloat16_as_ushort(h1) << 16);
}

DEV_INLINE uint32_t pack_f16(float f0, float f1) {
    __half2 h = __floats2half2_rn(f0, f1);
    return *(uint32_t*)&h;
}

DEV_INLINE void packsplit8(float4 a, float4 b, uint4& hi, uint4& lo) {
    hi.x = packsplit(a.x, a.y, lo.x);
    hi.y = packsplit(a.z, a.w, lo.y);
    hi.z = packsplit(b.x, b.y, lo.z);
    hi.w = packsplit(b.z, b.w, lo.w);
}

DEV_INLINE void mma_bf16(float* d, const uint32_t* a, const uint32_t* b) {
    asm volatile(
        "mma.sync.aligned.m16n8k16.row.col.f32.bf16.bf16.f32 "
        "{%0,%1,%2,%3}, {%4,%5,%6,%7}, {%8,%9}, {%0,%1,%2,%3};"
        : "+f"(d[0]), "+f"(d[1]), "+f"(d[2]), "+f"(d[3])
        : "r"(a[0]), "r"(a[1]), "r"(a[2]), "r"(a[3]),
          "r"(b[0]), "r"(b[1]));
}

DEV_INLINE void mma_f16(float* d, const uint32_t* a, const uint32_t* b) {
    asm volatile(
        "mma.sync.aligned.m16n8k16.row.col.f32.f16.f16.f32 "
        "{%0,%1,%2,%3}, {%4,%5,%6,%7}, {%8,%9}, {%0,%1,%2,%3};"
        : "+f"(d[0]), "+f"(d[1]), "+f"(d[2]), "+f"(d[3])
        : "r"(a[0]), "r"(a[1]), "r"(a[2]), "r"(a[3]),
          "r"(b[0]), "r"(b[1]));
}

DEV_INLINE void ldsm_x4(uint32_t& r0, uint32_t& r1, uint32_t& r2, uint32_t& r3,
                        uint32_t addr) {
    asm volatile("ldmatrix.sync.aligned.m8n8.x4.shared.b16 {%0,%1,%2,%3}, [%4];"
                 : "=r"(r0), "=r"(r1), "=r"(r2), "=r"(r3) : "r"(addr));
}

DEV_INLINE void cp_async16(uint32_t dst, const void* src) {
    asm volatile("cp.async.cg.shared.global [%0], [%1], 16;" :: "r"(dst), "l"(src));
}
DEV_INLINE void cp_commit() { asm volatile("cp.async.commit_group;"); }
template<int N> DEV_INLINE void cp_wait() {
    asm volatile("cp.async.wait_group %0;" :: "n"(N));
}

// ---------------- one-shot mega weight split ----------------
constexpr int SEG0 = H2 * K2_M;
constexpr int SEG1 = Hh * K2_DT;
constexpr int SEG2 = Mdim * K2_H;
constexpr int SEG3 = LXR * K2_H;
constexpr int Q0 = SEG0 / 4;
constexpr int Q1 = SEG1 / 4;
constexpr int Q2 = SEG2 / 4;
constexpr int Q3 = SEG3 / 4;
constexpr int QT = Q0 + Q1 + Q2 + Q3;
constexpr int QH = (Vv * K2_M) / 4;
constexpr int QALL = 2 * QT + QH;

__global__ void split_all_kernel(const float* __restrict__ liw,
                                 const float* __restrict__ ldw,
                                 const float* __restrict__ low,
                                 const float* __restrict__ lxw,
                                 const float* __restrict__ hw,
                                 uint32_t* __restrict__ liw_h, uint32_t* __restrict__ liw_l,
                                 uint32_t* __restrict__ ldw_h, uint32_t* __restrict__ ldw_l,
                                 uint32_t* __restrict__ low_h, uint32_t* __restrict__ low_l,
                                 uint32_t* __restrict__ lxw_h, uint32_t* __restrict__ lxw_l,
                                 uint32_t* __restrict__ hw_h) {
    int idx = blockIdx.x * blockDim.x + threadIdx.x;
    if (idx >= QALL) return;
    if (idx >= 2 * QT) {
        int u = (idx - 2 * QT) * 4;
        int r = u / K2_M, j = u - r * K2_M;
        const float4* p = (const float4*)(hw + (size_t)r * Mdim + 2 * j);
        float4 a = p[0], b = p[1];
        uint4 o;
        o.x = pack_f16(a.x, a.y);
        o.y = pack_f16(a.z, a.w);
        o.z = pack_f16(b.x, b.y);
        o.w = pack_f16(b.z, b.w);
        *(uint4*)(hw_h + u) = o;
        return;
    }
    int l = (idx >= QT) ? 1 : 0;
    int q = idx - l * QT;
    if (q < Q0) {
        int u = q * 4;
        int r = u / K2_M, j = u - r * K2_M;
        const float4* p = (const float4*)(liw + (size_t)l * H2 * Mdim + (size_t)r * Mdim + 2 * j);
        uint4 hi, lo;
        packsplit8(p[0], p[1], hi, lo);
        *(uint4*)(liw_h + (size_t)l * SEG0 + u) = hi;
        *(uint4*)(liw_l + (size_t)l * SEG0 + u) = lo;
    } else if (q < Q0 + Q1) {
        int u = (q - Q0) * 4;
        int r = u / K2_DT, j = u - r * K2_DT;
        uint4 hi, lo;
        if (2 * j >= Rr) {
            hi = make_uint4(0, 0, 0, 0);
            lo = make_uint4(0, 0, 0, 0);
        } else {
            const float4* p = (const float4*)(ldw + (size_t)l * Hh * Rr + (size_t)r * Rr + 2 * j);
            packsplit8(p[0], p[1], hi, lo);
        }
        *(uint4*)(ldw_h + (size_t)l * SEG1 + u) = hi;
        *(uint4*)(ldw_l + (size_t)l * SEG1 + u) = lo;
    } else if (q < Q0 + Q1 + Q2) {
        int u = (q - Q0 - Q1) * 4;
        int r = u / K2_H, j = u - r * K2_H;
        const float4* p = (const float4*)(low + (size_t)l * Mdim * Hh + (size_t)r * Hh + 2 * j);
        uint4 hi, lo;
        packsplit8(p[0], p[1], hi, lo);
        *(uint4*)(low_h + (size_t)l * SEG2 + u) = hi;
        *(uint4*)(low_l + (size_t)l * SEG2 + u) = lo;
    } else {
        int u = (q - Q0 - Q1 - Q2) * 4;
        int r = u / K2_H, j = u - r * K2_H;
        uint4 hi, lo;
        if (r >= XD) {
            hi = make_uint4(0, 0, 0, 0);
            lo = make_uint4(0, 0, 0, 0);
        } else {
            const float4* p = (const float4*)(lxw + (size_t)l * XD * Hh + (size_t)r * Hh + 2 * j);
            packsplit8(p[0], p[1], hi, lo);
        }
        *(uint4*)(lxw_h + (size_t)l * SEG3 + u) = hi;
        *(uint4*)(lxw_l + (size_t)l * SEG3 + u) = lo;
    }
}

// ---------------- embedding gather + planes ----------------
__global__ void embed_kernel(const int* __restrict__ ids,
                             const float* __restrict__ emb,
                             float* __restrict__ x,
                             uint32_t* __restrict__ xph,
                             uint32_t* __restrict__ xpl) {
    int idx = blockIdx.x * blockDim.x + threadIdx.x;
    if (idx >= BS * K2_M) return;
    int row = idx / K2_M;
    int m2  = idx - row * K2_M;
    const float* e = emb + (size_t)ids[row] * Mdim + 2 * m2;
    float f0 = e[0], f1 = e[1];
    x[(size_t)row * Mdim + 2 * m2]     = f0;
    x[(size_t)row * Mdim + 2 * m2 + 1] = f1;
    uint32_t l;
    uint32_t h = packsplit(f0, f1, l);
    xph[idx] = h;
    xpl[idx] = l;
}

// ---------------- bf16x3 GEMM, 2-stage double buffer, 2 CTAs/SM ----------
template<int BN, int ACT>
__global__ __launch_bounds__(256, 2)
void gemm_bf16x3(const uint32_t* __restrict__ Ah, const uint32_t* __restrict__ Al,
                 const uint32_t* __restrict__ Wh, const uint32_t* __restrict__ Wl,
                 int K2,
                 const float* __restrict__ bias,
                 float* __restrict__ C, int ldc) {
    constexpr int NTt  = BN / 32;
    constexpr int ROWB = 80;
    constexpr int APB  = 128 * ROWB;
    constexpr int WPB  = BN * ROWB;
    constexpr int STGB = 2 * APB + 2 * WPB;
    constexpr int NCH  = (256 + 2 * BN) * 4 / 256;

    extern __shared__ __align__(16) uint32_t smu[];

    const int tid  = threadIdx.x;
    const int lane = tid & 31;
    const int wid  = tid >> 5;
    const int wm   = wid >> 2;
    const int wn   = wid & 3;
    const int i0   = blockIdx.y * 128;
    const int j0   = blockIdx.x * BN;
    const int lq   = lane & 3;
    const int lg   = lane >> 2;

    const uint32_t sb = (uint32_t)__cvta_generic_to_shared(smu);

    const uint32_t* src[NCH];
    uint32_t dst[NCH];
    #pragma unroll
    for (int uu = 0; uu < NCH; uu++) {
        int c  = uu * 256 + tid;
        int r2 = c >> 2;
        int q  = c & 3;
        const uint32_t* gbase;
        int pofs, r;
        if (r2 < 128)            { r = r2;            gbase = Ah + (size_t)i0 * K2; pofs = 0; }
        else if (r2 < 256)       { r = r2 - 128;      gbase = Al + (size_t)i0 * K2; pofs = APB; }
        else if (r2 < 256 + BN)  { r = r2 - 256;      gbase = Wh + (size_t)j0 * K2; pofs = 2 * APB; }
        else                     { r = r2 - 256 - BN; gbase = Wl + (size_t)j0 * K2; pofs = 2 * APB + WPB; }
        src[uu] = gbase + (size_t)r * K2 + q * 4;
        dst[uu] = sb + pofs + r * ROWB + q * 16;
    }

    const uint32_t aRow = (uint32_t)((wm * 64 + (lane & 15)) * ROWB + ((lane >> 4) << 4));
    const uint32_t bRow = (uint32_t)((wn * (NTt * 8) + ((lane >> 4) << 3) + (lane & 7)) * ROWB
                                     + (((lane >> 3) & 1) << 4));

    float acc[4][NTt][4];
    #pragma unroll
    for (int m = 0; m < 4; m++)
        #pragma unroll
        for (int n = 0; n < NTt; n++)
            #pragma unroll
            for (int c = 0; c < 4; c++) acc[m][n][c] = 0.f;

    const int nk = K2 >> 4;

    #pragma unroll
    for (int uu = 0; uu < NCH; uu++) cp_async16(dst[uu], src[uu]);
    cp_commit();

    for (int t = 0; t < nk; t++) {
        cp_wait<0>();
        __syncthreads();
        if (t + 1 < nk) {
            uint32_t so = (uint32_t)((t + 1) & 1) * STGB;
            int ko = (t + 1) * 16;
            #pragma unroll
            for (int uu = 0; uu < NCH; uu++)
                cp_async16(dst[uu] + so, src[uu] + ko);
            cp_commit();
        }

        const uint32_t st = sb + (uint32_t)(t & 1) * STGB;

        #pragma unroll
        for (int h = 0; h < 2; h++) {
            uint32_t ah[4][4], al[4][4], bh[NTt][2], bl[NTt][2];
            #pragma unroll
            for (int m = 0; m < 4; m++) {
                uint32_t a0 = st + aRow + m * (16 * ROWB) + h * 32;
                ldsm_x4(ah[m][0], ah[m][1], ah[m][2], ah[m][3], a0);
                ldsm_x4(al[m][0], al[m][1], al[m][2], al[m][3], a0 + APB);
            }
            #pragma unroll
            for (int j = 0; j < NTt / 2; j++) {
                uint32_t b0 = st + 2 * APB + bRow + j * (16 * ROWB) + h * 32;
                ldsm_x4(bh[2*j][0], bh[2*j][1], bh[2*j+1][0], bh[2*j+1][1], b0);
                ldsm_x4(bl[2*j][0], bl[2*j][1], bl[2*j+1][0], bl[2*j+1][1], b0 + WPB);
            }
            #pragma unroll
            for (int m = 0; m < 4; m++)
                #pragma unroll
                for (int n = 0; n < NTt; n++)
                    mma_bf16(acc[m][n], ah[m], bh[n]);
            #pragma unroll
            for (int m = 0; m < 4; m++)
                #pragma unroll
                for (int n = 0; n < NTt; n++)
                    mma_bf16(acc[m][n], ah[m], bl[n]);
            #pragma unroll
            for (int m = 0; m < 4; m++)
                #pragma unroll
                for (int n = 0; n < NTt; n++)
                    mma_bf16(acc[m][n], al[m], bh[n]);
        }
    }

    #pragma unroll
    for (int m = 0; m < 4; m++) {
        int gi = i0 + wm * 64 + m * 16 + lg;
        #pragma unroll
        for (int n = 0; n < NTt; n++) {
            int gj = j0 + wn * (NTt * 8) + n * 8 + 2 * lq;
            float b0 = bias[gj], b1 = bias[gj + 1];
            float v0 = acc[m][n][0] + b0;
            float v1 = acc[m][n][1] + b1;
            float v2 = acc[m][n][2] + b0;
            float v3 = acc[m][n][3] + b1;
            if (ACT == 1) {
                v0 = softplusf(v0); v1 = softplusf(v1);
                v2 = softplusf(v2); v3 = softplusf(v3);
            }
            *(float2*)(C + (size_t)gi * ldc + gj)       = make_float2(v0, v1);
            *(float2*)(C + (size_t)(gi + 8) * ldc + gj) = make_float2(v2, v3);
        }
    }
}

// ---------------- fp16 head GEMM: BM=256, 512 threads, 3-stage ------------
__global__ __launch_bounds__(512, 1)
void gemm_fp16_256(const uint32_t* __restrict__ Ah, const uint32_t* __restrict__ Wh,
                   int K2,
                   const float* __restrict__ bias,
                   float* __restrict__ C, int ldc) {
    constexpr int BN   = 128;
    constexpr int NTt  = 4;
    constexpr int ROWB = 80;
    constexpr int APB  = 256 * ROWB;        // A: 256 rows
    constexpr int WPB  = BN * ROWB;
    constexpr int STGB = APB + WPB;
    constexpr int NCH  = (256 + BN) * 4 / 512;   // 3

    extern __shared__ __align__(16) uint32_t smu[];

    const int tid  = threadIdx.x;
    const int lane = tid & 31;
    const int wid  = tid >> 5;          // 0..15
    const int wm   = wid >> 2;          // 0..3  (64-row slices of 256)
    const int wn   = wid & 3;           // 0..3  (32-col slices of 128)
    const int i0   = blockIdx.y * 256;
    const int j0   = blockIdx.x * BN;
    const int lq   = lane & 3;
    const int lg   = lane >> 2;

    const uint32_t sb = (uint32_t)__cvta_generic_to_shared(smu);

    const uint32_t* src[NCH];
    uint32_t dst[NCH];
    #pragma unroll
    for (int uu = 0; uu < NCH; uu++) {
        int c  = uu * 512 + tid;
        int r2 = c >> 2;                // 0..383
        int q  = c & 3;
        const uint32_t* gbase;
        int pofs, r;
        if (r2 < 256) { r = r2;       gbase = Ah + (size_t)i0 * K2; pofs = 0; }
        else          { r = r2 - 256; gbase = Wh + (size_t)j0 * K2; pofs = APB; }
        src[uu] = gbase + (size_t)r * K2 + q * 4;
        dst[uu] = sb + pofs + r * ROWB + q * 16;
    }

    const uint32_t aRow = (uint32_t)((wm * 64 + (lane & 15)) * ROWB + ((lane >> 4) << 4));
    const uint32_t bRow = (uint32_t)((wn * 32 + ((lane >> 4) << 3) + (lane & 7)) * ROWB
                                     + (((lane >> 3) & 1) << 4));

    float acc[4][NTt][4];
    #pragma unroll
    for (int m = 0; m < 4; m++)
        #pragma unroll
        for (int n = 0; n < NTt; n++)
            #pragma unroll
            for (int c = 0; c < 4; c++) acc[m][n][c] = 0.f;

    const int nk = K2 >> 4;

    #pragma unroll
    for (int uu = 0; uu < NCH; uu++) cp_async16(dst[uu], src[uu]);
    cp_commit();
    #pragma unroll
    for (int uu = 0; uu < NCH; uu++) cp_async16(dst[uu] + STGB, src[uu] + 16);
    cp_commit();

    for (int t = 0; t < nk; t++) {
        if (t + 1 < nk) { cp_wait<1>(); } else { cp_wait<0>(); }
        __syncthreads();
        if (t + 2 < nk) {
            uint32_t so = (uint32_t)((t + 2) % 3) * STGB;
            int ko = (t + 2) * 16;
            #pragma unroll
            for (int uu = 0; uu < NCH; uu++)
                cp_async16(dst[uu] + so, src[uu] + ko);
            cp_commit();
        }

        const uint32_t st = sb + (uint32_t)(t % 3) * STGB;

        uint32_t ah2[2][4][4], bh2[2][NTt][2];
        #pragma unroll
        for (int h = 0; h < 2; h++) {
            #pragma unroll
            for (int m = 0; m < 4; m++) {
                uint32_t a0 = st + aRow + m * (16 * ROWB) + h * 32;
                ldsm_x4(ah2[h][m][0], ah2[h][m][1], ah2[h][m][2], ah2[h][m][3], a0);
            }
            #pragma unroll
            for (int j = 0; j < NTt / 2; j++) {
                uint32_t b0 = st + APB + bRow + j * (16 * ROWB) + h * 32;
                ldsm_x4(bh2[h][2*j][0], bh2[h][2*j][1],
                        bh2[h][2*j+1][0], bh2[h][2*j+1][1], b0);
            }
        }
        #pragma unroll
        for (int h = 0; h < 2; h++)
            #pragma unroll
            for (int m = 0; m < 4; m++)
                #pragma unroll
                for (int n = 0; n < NTt; n++)
                    mma_f16(acc[m][n], ah2[h][m], bh2[h][n]);
    }

    #pragma unroll
    for (int m = 0; m < 4; m++) {
        int gi = i0 + wm * 64 + m * 16 + lg;
        #pragma unroll
        for (int n = 0; n < NTt; n++) {
            int gj = j0 + wn * 32 + n * 8 + 2 * lq;
            float b0 = bias[gj], b1 = bias[gj + 1];
            *(float2*)(C + (size_t)gi * ldc + gj) =
                make_float2(acc[m][n][0] + b0, acc[m][n][1] + b1);
            *(float2*)(C + (size_t)(gi + 8) * ldc + gj) =
                make_float2(acc[m][n][2] + b0, acc[m][n][3] + b1);
        }
    }
}

// ---------------- conv + silu -> ures + u planes + dt pad zero ------------
__global__ void conv_silu_kernel(const float* __restrict__ xr,
                                 const float* __restrict__ cw,
                                 const float* __restrict__ cb,
                                 float2* __restrict__ ures,
                                 uint32_t* __restrict__ uh,
                                 uint32_t* __restrict__ ul,
                                 uint32_t* __restrict__ dth,
                                 uint32_t* __restrict__ dtl) {
    int idx = blockIdx.x * blockDim.x + threadIdx.x;
    if (idx >= BS * K2_H) return;
    int row = idx / K2_H;
    int h2  = idx - row * K2_H;
    int h   = 2 * h2;
    int s   = row % Ss;
    int b   = row / Ss;

    const float4* cw4 = (const float4*)cw;
    float4 ta = cw4[h], tb = cw4[h + 1];
    float a0 = cb[h], a1 = cb[h + 1];
    #pragma unroll
    for (int k = 0; k < 4; k++) {
        int sp = s - 3 + k;
        if (sp >= 0) {
            float2 xv = *(const float2*)(xr + (size_t)(b * Ss + sp) * H2 + h);
            float wa = (k == 0) ? ta.x : (k == 1) ? ta.y : (k == 2) ? ta.z : ta.w;
            float wb = (k == 0) ? tb.x : (k == 1) ? tb.y : (k == 2) ? tb.z : tb.w;
            a0 += wa * xv.x;
            a1 += wb * xv.y;
        }
    }
    float u0 = silu_fast(a0), u1 = silu_fast(a1);
    float2 rv = *(const float2*)(xr + (size_t)row * H2 + Hh + h);
    *(float4*)(ures + (size_t)row * Hh + h) = make_float4(u0, rv.x, u1, rv.y);
    uint32_t lo;
    uint32_t hi = packsplit(u0, u1, lo);
    uh[idx] = hi;
    ul[idx] = lo;
    if (h2 < 8) {
        dth[(size_t)row * K2_DT + 24 + h2] = 0;
        dtl[(size_t)row * K2_DT + 24 + h2] = 0;
    }
}

// ---------------- post-linx: dt scatter only ----------------
__global__ void post_linx_kernel(const float* __restrict__ xw,
                                 const float* __restrict__ lxb,
                                 uint32_t* __restrict__ dth,
                                 uint32_t* __restrict__ dtl) {
    int idx = blockIdx.x * blockDim.x + threadIdx.x;
    if (idx >= BS * 24) return;
    int row = idx / 24;
    int p   = idx - row * 24;
    int j0  = 2 * p;
    float v0 = xw[(size_t)row * LXR + j0]     + lxb[j0];
    float v1 = xw[(size_t)row * LXR + j0 + 1] + lxb[j0 + 1];
    uint32_t lo;
    uint32_t hi = packsplit(v0, v1, lo);
    dth[(size_t)row * K2_DT + p] = hi;
    dtl[(size_t)row * K2_DT + p] = lo;
}

// ---------------- scan + gate, depth-4 prefetch; B/C from xw directly ------
__global__ void scan_gate_kernel(const float* __restrict__ delta,
                                 const float2* __restrict__ ures,
                                 const float* __restrict__ xw,
                                 const float* __restrict__ lxb,
                                 const float* __restrict__ Dp,
                                 uint32_t* __restrict__ yh,
                                 uint32_t* __restrict__ yl) {
    int gwarp = (blockIdx.x * blockDim.x + threadIdx.x) >> 5;
    if (gwarp >= Bb * (Hh / 2)) return;
    int lane = threadIdx.x & 31;
    int half = lane >> 4;
    int n    = lane & 15;
    int b    = gwarp / (Hh / 2);
    int hp   = gwarp % (Hh / 2);
    int h    = hp * 2 + half;

    const float An = -(float)(n + 1);
    const float Dh = Dp[h];
    const float bB = lxb[Rr + n];
    const float bC = lxb[Rr + Nn + n];
    float state = 0.f;

    const int base = b * Ss;

    float  pd[4], pB[4], pC[4];
    float2 pu[4];
    #pragma unroll
    for (int k = 0; k < 4; k++) {
        int r = base + k;
        pd[k] = __ldg(delta + (size_t)r * Hh + h);
        pu[k] = __ldg(ures + (size_t)r * Hh + h);
        pB[k] = __ldg(xw + (size_t)r * LXR + Rr + n) + bB;
        pC[k] = __ldg(xw + (size_t)r * LXR + Rr + Nn + n) + bC;
    }

    float dA  = __expf(pd[0] * An);
    float dBu = pd[0] * pB[0] * pu[0].x;

    #pragma unroll 4
    for (int s = 0; s < Ss; s++) {
        const int slot = s & 3;
        const int ns   = (s + 1) & 3;
        int row = base + s;

        float uv  = pu[slot].x;
        float res = pu[slot].y;
        float Cn  = pC[slot];

        state = dA * state + dBu;

        if (s + 4 < Ss) {
            int r = row + 4;
            pd[slot] = __ldg(delta + (size_t)r * Hh + h);
            pu[slot] = __ldg(ures + (size_t)r * Hh + h);
            pB[slot] = __ldg(xw + (size_t)r * LXR + Rr + n) + bB;
            pC[slot] = __ldg(xw + (size_t)r * LXR + Rr + Nn + n) + bC;
        }

        dA  = __expf(pd[ns] * An);
        dBu = pd[ns] * pB[ns] * pu[ns].x;

        float val = state * Cn;
        val += __shfl_xor_sync(0xffffffffu, val, 8);
        val += __shfl_xor_sync(0xffffffffu, val, 4);
        val += __shfl_xor_sync(0xffffffffu, val, 2);
        val += __shfl_xor_sync(0xffffffffu, val, 1);
        float yv = (val + uv * Dh) * silu_fast(res);
        float y1 = __shfl_sync(0xffffffffu, yv, 16);
        if (lane == 0) {
            uint32_t lo;
            uint32_t hi = packsplit(yv, y1, lo);
            yh[(size_t)row * K2_H + hp] = hi;
            yl[(size_t)row * K2_H + hp] = lo;
        }
    }
}

// ---------------- x += rmsnorm(mo) * w ; emit x planes ----------------
__global__ void rmsnorm_add_kernel(float* __restrict__ x,
                                   const float* __restrict__ mo,
                                   const float* __restrict__ w,
                                   uint32_t* __restrict__ xph,
                                   uint32_t* __restrict__ xpl) {
    int row = blockIdx.x;
    const float* r = mo + (size_t)row * Mdim;
    float ss = 0.f;
    for (int m = threadIdx.x; m < Mdim; m += blockDim.x) {
        float v = r[m];
        ss += v * v;
    }
    __shared__ float sh[8];
    ss = warp_sum(ss);
    int wid = threadIdx.x >> 5, lane = threadIdx.x & 31;
    if (lane == 0) sh[wid] = ss;
    __syncthreads();
    if (wid == 0) {
        float v = (lane < (int)(blockDim.x >> 5)) ? sh[lane] : 0.f;
        v = warp_sum(v);
        if (lane == 0) sh[0] = v;
    }
    __syncthreads();
    float scale = rsqrtf(sh[0] / (float)Mdim + 1e-15f);
    float* xp = x + (size_t)row * Mdim;
    for (int m2 = threadIdx.x; m2 < K2_M; m2 += blockDim.x) {
        int m = 2 * m2;
        float v0 = xp[m]     + r[m]     * scale * w[m];
        float v1 = xp[m + 1] + r[m + 1] * scale * w[m + 1];
        xp[m] = v0; xp[m + 1] = v1;
        uint32_t lo;
        uint32_t hi = packsplit(v0, v1, lo);
        xph[(size_t)row * K2_M + m2] = hi;
        xpl[(size_t)row * K2_M + m2] = lo;
    }
}

// ---------------- final rmsnorm -> fp16 planes (head input) ----------------
__global__ void rmsnorm_final_kernel(const float* __restrict__ x,
                                     const float* __restrict__ w,
                                     uint32_t* __restrict__ xnf) {
    int row = blockIdx.x;
    const float* r = x + (size_t)row * Mdim;
    float ss = 0.f;
    for (int m = threadIdx.x; m < Mdim; m += blockDim.x) {
        float v = r[m];
        ss += v * v;
    }
    __shared__ float sh[8];
    ss = warp_sum(ss);
    int wid = threadIdx.x >> 5, lane = threadIdx.x & 31;
    if (lane == 0) sh[wid] = ss;
    __syncthreads();
    if (wid == 0) {
        float v = (lane < (int)(blockDim.x >> 5)) ? sh[lane] : 0.f;
        v = warp_sum(v);
        if (lane == 0) sh[0] = v;
    }
    __syncthreads();
    float scale = rsqrtf(sh[0] / (float)Mdim + 1e-15f);
    for (int m2 = threadIdx.x; m2 < K2_M; m2 += blockDim.x) {
        int m = 2 * m2;
        xnf[(size_t)row * K2_M + m2] =
            pack_f16(r[m] * scale * w[m], r[m + 1] * scale * w[m + 1]);
    }
}

// ---------------- launch ----------------
extern "C" void kernel_launch(void* const* d_in, const int* in_sizes, int n_in,
                              void* d_out, int out_size) {
    const int*   ids = (const int*)  d_in[0];
    const float* emb = (const float*)d_in[1];
    const float* liw = (const float*)d_in[2];
    const float* lib = (const float*)d_in[3];
    const float* cw  = (const float*)d_in[4];
    const float* cb  = (const float*)d_in[5];
    const float* lxw = (const float*)d_in[6];
    const float* lxb = (const float*)d_in[7];
    const float* ldw = (const float*)d_in[8];
    const float* ldb = (const float*)d_in[9];
    const float* low = (const float*)d_in[10];
    const float* lob = (const float*)d_in[11];
    const float* Dp  = (const float*)d_in[12];
    const float* bnw = (const float*)d_in[13];
    const float* fnw = (const float*)d_in[14];
    const float* hw  = (const float*)d_in[15];
    const float* hb  = (const float*)d_in[16];
    float* out = (float*)d_out;

    float *x, *xr, *delta, *mo, *xw, *zb;
    float2 *ures;
    cudaGetSymbolAddress((void**)&x,     g_x);
    cudaGetSymbolAddress((void**)&xr,    g_xr);
    cudaGetSymbolAddress((void**)&delta, g_delta);
    cudaGetSymbolAddress((void**)&mo,    g_mo);
    cudaGetSymbolAddress((void**)&xw,    g_xw);
    cudaGetSymbolAddress((void**)&zb,    g_zb);
    cudaGetSymbolAddress((void**)&ures,  g_ures);

    uint32_t *xp_h, *xp_l, *uh, *ul, *act_h, *act_l;
    uint32_t *liw_h, *liw_l, *ldw_h, *ldw_l, *low_h, *low_l, *lxw_h, *lxw_l, *hw_h;
    cudaGetSymbolAddress((void**)&xp_h,  g_xp_h);
    cudaGetSymbolAddress((void**)&xp_l,  g_xp_l);
    cudaGetSymbolAddress((void**)&uh,    g_uh);
    cudaGetSymbolAddress((void**)&ul,    g_ul);
    cudaGetSymbolAddress((void**)&act_h, g_act_h);
    cudaGetSymbolAddress((void**)&act_l, g_act_l);
    cudaGetSymbolAddress((void**)&liw_h, g_liw_h);
    cudaGetSymbolAddress((void**)&liw_l, g_liw_l);
    cudaGetSymbolAddress((void**)&ldw_h, g_ldw_h);
    cudaGetSymbolAddress((void**)&ldw_l, g_ldw_l);
    cudaGetSymbolAddress((void**)&low_h, g_low_h);
    cudaGetSymbolAddress((void**)&low_l, g_low_l);
    cudaGetSymbolAddress((void**)&lxw_h, g_lxw_h);
    cudaGetSymbolAddress((void**)&lxw_l, g_lxw_l);
    cudaGetSymbolAddress((void**)&hw_h,  g_hw_h);

    const int SM128  = 2 * (2 * 128 * 80 + 2 * 128 * 80);  // 81920
    const int SM64   = 2 * (2 * 128 * 80 + 2 * 64 * 80);   // 61440
    const int SMF256 = 3 * (256 + 128) * 80;               // 92160
    cudaFuncSetAttribute((const void*)gemm_bf16x3<128, 0>,
                         cudaFuncAttributeMaxDynamicSharedMemorySize, SM128);
    cudaFuncSetAttribute((const void*)gemm_bf16x3<128, 1>,
                         cudaFuncAttributeMaxDynamicSharedMemorySize, SM128);
    cudaFuncSetAttribute((const void*)gemm_bf16x3<64, 0>,
                         cudaFuncAttributeMaxDynamicSharedMemorySize, SM64);
    cudaFuncSetAttribute((const void*)gemm_fp16_256,
                         cudaFuncAttributeMaxDynamicSharedMemorySize, SMF256);

    embed_kernel<<<(BS * K2_M + 255) / 256, 256>>>(ids, emb, x, xp_h, xp_l);
    split_all_kernel<<<(QALL + 255) / 256, 256>>>(
        liw, ldw, low, lxw, hw,
        liw_h, liw_l, ldw_h, ldw_l, low_h, low_l, lxw_h, lxw_l, hw_h);

    for (int l = 0; l < Ll; l++) {
        gemm_bf16x3<128, 0><<<dim3(H2 / 128, BS / 128), 256, SM128>>>(
            xp_h, xp_l,
            liw_h + (size_t)l * SEG0, liw_l + (size_t)l * SEG0,
            K2_M, lib + (size_t)l * H2, xr, H2);

        conv_silu_kernel<<<(BS * K2_H + 255) / 256, 256>>>(
            xr, cw + (size_t)l * Hh * Kk, cb + (size_t)l * Hh,
            ures, uh, ul, act_h, act_l);

        gemm_bf16x3<64, 0><<<dim3(LXR / 64, BS / 128), 256, SM64>>>(
            uh, ul,
            lxw_h + (size_t)l * SEG3, lxw_l + (size_t)l * SEG3,
            K2_H, zb, xw, LXR);

        post_linx_kernel<<<(BS * 24 + 255) / 256, 256>>>(
            xw, lxb + (size_t)l * XD, act_h, act_l);

        gemm_bf16x3<128, 1><<<dim3(Hh / 128, BS / 128), 256, SM128>>>(
            act_h, act_l,
            ldw_h + (size_t)l * SEG1, ldw_l + (size_t)l * SEG1,
            K2_DT, ldb + (size_t)l * Hh, delta, Hh);

        scan_gate_kernel<<<(Bb * (Hh / 2) * 32 + 255) / 256, 256>>>(
            delta, ures, xw, lxb + (size_t)l * XD, Dp + (size_t)l * Hh,
            act_h, act_l);

        gemm_bf16x3<64, 0><<<dim3(Mdim / 64, BS / 128), 256, SM64>>>(
            act_h, act_l,
            low_h + (size_t)l * SEG2, low_l + (size_t)l * SEG2,
            K2_H, lob + (size_t)l * Mdim, mo, Mdim);

        rmsnorm_add_kernel<<<BS, 256>>>(x, mo, bnw + (size_t)l * Mdim, xp_h, xp_l);
    }

    rmsnorm_final_kernel<<<BS, 256>>>(x, fnw, act_h);

    // head: fp16 BM=256 (halved W re-reads)
    gemm_fp16_256<<<dim3(Vv / 128, BS / 256), 512, SMF256>>>(
        act_h, hw_h, K2_M, hb, out, Vv);
}